// round 13
// baseline (speedup 1.0000x reference)
#include <cuda_runtime.h>
#include <cstdint>

// Problem constants
constexpr int B  = 8;
constexpr int C  = 19;
constexpr int H  = 320;
constexpr int W  = 2048;
constexpr int HH_OFF = 10;
constexpr int HH_N  = 10;
constexpr int WW   = 128;
constexpr int P    = HH_N * WW;      // 1280
constexpr long long NE = (long long)B * P * P;

constexpr int NT = 512;                  // threads per block

constexpr int WCHUNK = 512;              // label columns per pool block (2x R12)
constexpr int NWCH   = W / WCHUNK;       // 4
constexpr int POOL_PER_B = HH_N * NWCH;  // 40
constexpr int POOL_BLOCKS = B * POOL_PER_B;   // 320
constexpr int RWARPS = 16;               // rows per attn block
constexpr int ATTN_PER_B = P / RWARPS;   // 80
constexpr int ATTN_BLOCKS = B * ATTN_PER_B;   // 640
constexpr int CH = P / 4 / 32;           // 10 float4 chunks per lane

constexpr int ROW_BYTES   = P * 4;                // 5120
constexpr int SLICE_BYTES = RWARPS * ROW_BYTES;   // 81920
constexpr int SLICE_LINES = SLICE_BYTES / 128;    // 640

__device__ int g_lab[B * P];
__device__ int g_done[B];
__device__ int g_cons[B];

__device__ __forceinline__ int ld_relaxed_gpu(const int* p) {
    int v;
    asm volatile("ld.global.relaxed.gpu.b32 %0, [%1];" : "=r"(v) : "l"(p));
    return v;
}

__device__ __forceinline__ void prefetch_l2(const void* p) {
    asm volatile("prefetch.global.L2 [%0];" :: "l"(p));
}

// ---------------------------------------------------------------------------
// Fused kernel, 512-thread blocks. Blocks [0,320): pool+argmax (batch-major,
// all wave-1 resident -> no deadlock). Blocks [320,960): attn, round-robin
// batch mapping, 16 rows per block.
// ---------------------------------------------------------------------------
__global__ __launch_bounds__(NT) void fused_kernel(const float* __restrict__ label,
                                                   const float* __restrict__ energy,
                                                   float* __restrict__ out)
{
    const int bid = blockIdx.x;
    const int t   = threadIdx.x;

    __shared__ int lab_s[P];

    if (bid < POOL_BLOCKS) {
        // ================= POOL + ARGMAX =================
        const int b   = bid / POOL_PER_B;
        const int rem = bid % POOL_PER_B;
        const int hh  = rem / NWCH;
        const int wc  = rem % NWCH;
        const int f   = t & 127;   // 0..127 float4 within 512-col chunk
        const int cg  = t >> 7;    // 0..3

        float (*ssum)[33] = reinterpret_cast<float(*)[33]>(lab_s); // 19*33*4 = 2.5KB

        const int h0 = (HH_OFF + hh) * 16;
        const int row_f4 = W / 4;

#pragma unroll
        for (int c4 = 0; c4 < 5; c4++) {
            const int c = c4 * 4 + cg;
            float acc = 0.f;
            if (c < C) {
                const float4* p = reinterpret_cast<const float4*>(
                    label + (((size_t)b * C + c) * H + h0) * W + wc * WCHUNK) + f;
#pragma unroll
                for (int r = 0; r < 16; r++) {
                    float4 v = __ldcs(p + (size_t)r * row_f4);
                    acc += (v.x + v.y) + (v.z + v.w);
                }
            }
            acc += __shfl_xor_sync(0xffffffffu, acc, 1);
            acc += __shfl_xor_sync(0xffffffffu, acc, 2);
            if (c < C && (t & 3) == 0) ssum[c][f >> 2] = acc;
        }
        __syncthreads();

        if (t < 32) {
            float best = ssum[0][t];
            int bi = 0;
#pragma unroll
            for (int c = 1; c < C; c++) {
                float v = ssum[c][t];
                if (v > best) { best = v; bi = c; }   // strict '>' = first-max
            }
            g_lab[(b * HH_N + hh) * WW + wc * 32 + t] = bi;
        }
        __syncthreads();
        __threadfence();
        if (t == 0) atomicAdd(&g_done[b], 1);
    } else {
        // ================= ATTN (two-pass, warp-per-row, 16 rows) =========
        const int aid = bid - POOL_BLOCKS;
        const int b   = aid % B;                    // round-robin batches
        const int i0  = (aid / B) * RWARPS;
        const int wid = t >> 5;                     // 0..15
        const int lid = t & 31;

        // Prefetch this block's 80KB energy slice into L2 before polling.
        {
            const char* base = reinterpret_cast<const char*>(
                energy + ((size_t)b * P + i0) * P);
            prefetch_l2(base + (size_t)t * 128);
            if (t < SLICE_LINES - NT)
                prefetch_l2(base + (size_t)(t + NT) * 128);
        }

        if (t == 0) {
            while (ld_relaxed_gpu(&g_done[b]) < POOL_PER_B) __nanosleep(256);
        }
        __syncthreads();
        __threadfence();

        if (t < P / 4)
            reinterpret_cast<int4*>(lab_s)[t] =
                reinterpret_cast<const int4*>(g_lab + b * P)[t];
        __syncthreads();

        const int i  = i0 + wid;
        const int li = lab_s[i];

        const float4* erow = reinterpret_cast<const float4*>(
            energy + ((size_t)b * P + i) * P);
        float4* eout = reinterpret_cast<float4*>(out + ((size_t)b * P + i) * P);
        float4* aout = reinterpret_cast<float4*>(out + NE + ((size_t)b * P + i) * P);
        const int4* lab4 = reinterpret_cast<const int4*>(lab_s);

        // Pass 1: mask-edit, store e (regular store, L2-resident for pass 2),
        // accumulate exp-sum. No max-shift (values bounded ~|7|, f32 exp safe,
        // softmax shift-invariant).
        float s = 0.f;
#pragma unroll
        for (int k = 0; k < CH; k++) {
            const int j = lid + k * 32;
            float4 en = erow[j];
            int4  lj = lab4[j];

            float4 ev;
            ev.x = (lj.x == li) ? (en.x < 0.f ? 0.5f : en.x) : (en.x > 0.f ? -0.5f : en.x);
            ev.y = (lj.y == li) ? (en.y < 0.f ? 0.5f : en.y) : (en.y > 0.f ? -0.5f : en.y);
            ev.z = (lj.z == li) ? (en.z < 0.f ? 0.5f : en.z) : (en.z > 0.f ? -0.5f : en.z);
            ev.w = (lj.w == li) ? (en.w < 0.f ? 0.5f : en.w) : (en.w > 0.f ? -0.5f : en.w);

            eout[j] = ev;   // re-read in pass 2 (L2 hit)

            s += (__expf(ev.x) + __expf(ev.y)) + (__expf(ev.z) + __expf(ev.w));
        }

#pragma unroll
        for (int o = 16; o > 0; o >>= 1) s += __shfl_xor_sync(0xffffffffu, s, o);
        const float inv = 1.f / s;

        // Pass 2: reload ev from L2, recompute exp, single streaming store.
#pragma unroll
        for (int k = 0; k < CH; k++) {
            const int j = lid + k * 32;
            float4 ev = eout[j];
            float4 am;
            am.x = __expf(ev.x) * inv;
            am.y = __expf(ev.y) * inv;
            am.z = __expf(ev.z) * inv;
            am.w = __expf(ev.w) * inv;
            __stcs(aout + j, am);
        }

        // Self-reset for next graph replay.
        if (t == 0) {
            int old = atomicAdd(&g_cons[b], 1);
            if (old == ATTN_PER_B - 1) {
                g_done[b] = 0;
                g_cons[b] = 0;
            }
        }
    }
}

extern "C" void kernel_launch(void* const* d_in, const int* in_sizes, int n_in,
                              void* d_out, int out_size)
{
    const float* label  = (const float*)d_in[0];  // [8,19,320,2048] f32
    const float* energy = (const float*)d_in[1];  // [8,1280,1280]  f32
    float* out = (float*)d_out;                   // e then attention_map

    (void)in_sizes; (void)n_in; (void)out_size;

    fused_kernel<<<POOL_BLOCKS + ATTN_BLOCKS, NT>>>(label, energy, out);
}